// round 14
// baseline (speedup 1.0000x reference)
#include <cuda_runtime.h>

#define Bsz   32768
#define Lq    7
#define NSTEP 5
#define M1    (Bsz*NSTEP)          /* 163840 rows (b,t) t<5 */
#define BLq   (Bsz*Lq)             /* 229376 */
#define NEGV  -1000000000.0f
#define NBLK  640                  /* M1/256 */

// ------------- static device scratch (no allocation APIs anywhere) -------------
static __device__ float g_E  [(size_t)M1 * 256];   // edges
static __device__ float g_Z  [(size_t)M1 * 256];   // edge @ W_edge^T
static __device__ float g_qt [(size_t)Bsz * 256];
static __device__ float g_inp[(size_t)Bsz * 256];
static __device__ float g_ctx[(size_t)BLq * 256];  // (b*7+l, h)
static __device__ float g_att[BLq];
static __device__ float g_cmax[Lq];
static __device__ float g_csum[Lq];
static __device__ int   g_x64;                     // 1 if xes is int64 on device
static __device__ int   g_cntA[NBLK];              // per-block cond counts -> exclusive scan
static __device__ int   g_nA;                      // total cond rows
static __device__ int   g_perm[M1];                // bucket A rows [0,nA), bucket B [nA,M1)

// ------------- XLA/Eigen f32 tanh (rational approx, clamp 7.90531110763549805) ---
__device__ __forceinline__ float xtanh(float x) {
    float ax = fabsf(x);
    if (ax < 0.0004f) return x;
    float cx = fminf(fmaxf(x, -7.90531110763549805f), 7.90531110763549805f);
    float x2 = cx * cx;
    float p = fmaf(x2, -2.76076847742355e-16f, 2.00018790482477e-13f);
    p = fmaf(p, x2, -8.60467152213735e-11f);
    p = fmaf(p, x2,  5.12229709037114e-08f);
    p = fmaf(p, x2,  1.48572235717979e-05f);
    p = fmaf(p, x2,  6.37261928875436e-04f);
    p = fmaf(p, x2,  4.89352455891786e-03f);
    p = cx * p;
    float q = fmaf(x2, 1.19825839466702e-06f, 1.18534705686654e-04f);
    q = fmaf(q, x2, 2.26843463243900e-03f);
    q = fmaf(q, x2, 4.89352518554385e-03f);
    return __fdiv_rn(p, q);
}

// ------------- threefry2x32, key = (0, 42), 20 rounds ------------------------
#define TFR(r) { x0 += x1; x1 = (x1 << (r)) | (x1 >> (32 - (r))); x1 ^= x0; }
__device__ __forceinline__ void threefry42(unsigned c0, unsigned c1,
                                           unsigned& o0, unsigned& o1) {
    const unsigned ks0 = 0u, ks1 = 42u, ks2 = 0x1BD11BDAu ^ 0u ^ 42u;
    unsigned x0 = c0 + ks0, x1 = c1 + ks1;
    TFR(13) TFR(15) TFR(26) TFR(6)   x0 += ks1; x1 += ks2 + 1u;
    TFR(17) TFR(29) TFR(16) TFR(24)  x0 += ks2; x1 += ks0 + 2u;
    TFR(13) TFR(15) TFR(26) TFR(6)   x0 += ks0; x1 += ks1 + 3u;
    TFR(17) TFR(29) TFR(16) TFR(24)  x0 += ks1; x1 += ks2 + 4u;
    TFR(13) TFR(15) TFR(26) TFR(6)   x0 += ks2; x1 += ks0 + 5u;
    o0 = x0; o1 = x1;
}

__device__ __forceinline__ unsigned jax_bits(unsigned j) {
    unsigned o0, o1;
    threefry42(0u, j, o0, o1);      // partitionable threefry: bits = o0 ^ o1
    return o0 ^ o1;
}

// ------------- xes fetch (int64 vs int32, detected on device) ------------------
__device__ __forceinline__ void fetch_x(const void* xraw, int b, int t,
                                        int& hi, int& vi, int& tv) {
    if (g_x64) {
        const long long* xp = (const long long*)xraw + ((size_t)b * 6 + t) * 3;
        hi = (int)xp[0]; vi = (int)xp[1]; tv = (int)xp[2];
    } else {
        const int* xp = (const int*)xraw + ((size_t)b * 6 + t) * 3;
        hi = xp[0]; vi = xp[1]; tv = xp[2];
    }
}

__global__ void detect_kernel(const unsigned* __restrict__ x) {
    if (threadIdx.x == 0 && blockIdx.x == 0) {
        int a = 1;
        for (int k = 0; k < 256; k++)
            if (x[2 * k + 1] != 0u) { a = 0; break; }
        g_x64 = a;
    }
}

// ------------- bucketing: partition rows r=b*5+t by cond=(t_val==0) -----------
__global__ void bcount(const void* __restrict__ xraw) {
    int tid = threadIdx.x, blk = blockIdx.x;
    int r = blk * 256 + tid;
    int b = r / 5, t = r - b * 5;
    int hi, vi, tv; fetch_x(xraw, b, t, hi, vi, tv);
    int c = __syncthreads_count(tv == 0);
    if (tid == 0) g_cntA[blk] = c;
}

__global__ void bscan() {
    __shared__ int s[1024];
    int tid = threadIdx.x;
    int v = (tid < NBLK) ? g_cntA[tid] : 0;
    s[tid] = v; __syncthreads();
    for (int off = 1; off < 1024; off <<= 1) {
        int t = (tid >= off) ? s[tid - off] : 0;
        __syncthreads();
        s[tid] += t; __syncthreads();
    }
    if (tid < NBLK) g_cntA[tid] = s[tid] - v;     // exclusive
    if (tid == NBLK - 1) g_nA = s[tid];
}

__global__ void bscatter(const void* __restrict__ xraw) {
    int tid = threadIdx.x, blk = blockIdx.x;
    int r = blk * 256 + tid;
    int b = r / 5, t = r - b * 5;
    int hi, vi, tv; fetch_x(xraw, b, t, hi, vi, tv);
    bool cond = (tv == 0);
    unsigned m = __ballot_sync(0xffffffffu, cond);
    int lane = tid & 31, w = tid >> 5;
    __shared__ int wA[8], wOffA[8];
    int lrA = __popc(m & ((1u << lane) - 1u));
    if (lane == 0) wA[w] = __popc(m);
    __syncthreads();
    if (tid == 0) { int s = 0; for (int i = 0; i < 8; i++) { wOffA[i] = s; s += wA[i]; } }
    __syncthreads();
    int nA = g_nA;
    int baseA = g_cntA[blk];
    int baseB = blk * 256 - baseA;
    int lrB   = lane - lrA;
    int wOffB = w * 32 - wOffA[w];
    int pos = cond ? (baseA + wOffA[w] + lrA)
                   : (nA + baseB + wOffB + lrB);
    g_perm[pos] = r;
}

// ====== smem store helper macro (ping-pong buffers) ======
#define STORE_TILE(Abuf, Wbuf, v0, v1, u0, u1)                                   \
    Abuf[kq+0][lr]    = v0.x; Abuf[kq+1][lr]    = v0.y;                          \
    Abuf[kq+2][lr]    = v0.z; Abuf[kq+3][lr]    = v0.w;                          \
    Abuf[kq+0][lr+64] = v1.x; Abuf[kq+1][lr+64] = v1.y;                          \
    Abuf[kq+2][lr+64] = v1.z; Abuf[kq+3][lr+64] = v1.w;                          \
    Wbuf[kq+0][lr]    = u0.x; Wbuf[kq+1][lr]    = u0.y;                          \
    Wbuf[kq+2][lr]    = u0.z; Wbuf[kq+3][lr]    = u0.w;                          \
    Wbuf[kq+0][lr+64] = u1.x; Wbuf[kq+1][lr+64] = u1.y;                          \
    Wbuf[kq+2][lr+64] = u1.z; Wbuf[kq+3][lr+64] = u1.w;

#define COMPUTE_TILE(Abuf, Wbuf)                                                 \
    _Pragma("unroll")                                                            \
    for (int kk = 0; kk < 16; kk++) {                                            \
        float a[8], w[8];                                                        \
        *(float4*)(a)     = *(const float4*)&Abuf[kk][ty * 8];                   \
        *(float4*)(a + 4) = *(const float4*)&Abuf[kk][ty * 8 + 4];               \
        *(float4*)(w)     = *(const float4*)&Wbuf[kk][tx * 4];                   \
        *(float4*)(w + 4) = *(const float4*)&Wbuf[kk][tx * 4 + 64];              \
        _Pragma("unroll")                                                        \
        for (int i = 0; i < 8; i++)                                              \
            _Pragma("unroll")                                                    \
            for (int j = 0; j < 8; j++)                                          \
                acc[i][j] = fmaf(a[i], w[j], acc[i][j]);                         \
    }

// ------------- bucketed edge GEMM, K=256, 128x128 tile, BK=16, ping-pong ------
// Per-output chain is k-ascending fmaf: bit-identical to the reference per-gemm
// chain. Two passes (h then v-add) reproduce "gemm1 + gemm2" exactly.
__global__ void __launch_bounds__(256)
edge_gemm(const float* __restrict__ enc, const void* __restrict__ xraw,
          const float* __restrict__ Wcond, const float* __restrict__ Wother,
          int xcol, int addmode) {
    __shared__ float As[2][16][132];
    __shared__ float Wsm[2][16][132];
    __shared__ const float* Ap[128];
    __shared__ int rowR[128];

    const int tid  = threadIdx.x;
    const int tile = blockIdx.x;
    const int col0 = blockIdx.y * 128;

    const int nA = g_nA, nB = M1 - nA;
    const int tilesA = (nA + 127) >> 7;
    const int tilesB = (nB + 127) >> 7;
    if (tile >= tilesA + tilesB) return;
    const bool bb = (tile >= tilesA);

    if (tid < 128) {
        int j   = bb ? (tile - tilesA) * 128 + tid : tile * 128 + tid;
        int cnt = bb ? nB : nA;
        int r = -1;
        const float* ap = enc;
        if (j < cnt) {
            r = g_perm[bb ? nA + j : j];
            int b = r / 5, t = r - b * 5;
            int hi, vi, tv; fetch_x(xraw, b, t, hi, vi, tv);
            int sel = xcol ? vi : hi;
            ap = enc + ((size_t)b * 7 + sel) * 256;
        }
        rowR[tid] = r; Ap[tid] = ap;
    }
    __syncthreads();

    const float* W = bb ? Wother : Wcond;
    const int lr = tid >> 2;            // 0..63
    const int kq = (tid & 3) * 4;       // 0,4,8,12
    const int tx = tid & 15, ty = tid >> 4;

    const float* a0 = Ap[lr]      + kq;
    const float* a1 = Ap[lr + 64] + kq;
    const float* w0 = W + (size_t)(col0 + lr) * 256 + kq;
    const float* w1 = W + (size_t)(col0 + lr + 64) * 256 + kq;

    float acc[8][8];
#pragma unroll
    for (int i = 0; i < 8; i++)
#pragma unroll
        for (int j = 0; j < 8; j++) acc[i][j] = 0.f;

    {   // prime buffer 0
        float4 ga0 = *(const float4*)a0;
        float4 ga1 = *(const float4*)a1;
        float4 gw0 = *(const float4*)w0;
        float4 gw1 = *(const float4*)w1;
        STORE_TILE(As[0], Wsm[0], ga0, ga1, gw0, gw1)
    }
    __syncthreads();

    int buf = 0;
#pragma unroll
    for (int k0 = 0; k0 < 256; k0 += 16) {
        float4 na0, na1, nw0, nw1;
        const bool more = (k0 + 16 < 256);
        if (more) {
            na0 = *(const float4*)(a0 + k0 + 16);
            na1 = *(const float4*)(a1 + k0 + 16);
            nw0 = *(const float4*)(w0 + k0 + 16);
            nw1 = *(const float4*)(w1 + k0 + 16);
        }
        if (buf == 0) { COMPUTE_TILE(As[0], Wsm[0]) }
        else          { COMPUTE_TILE(As[1], Wsm[1]) }
        if (more) {
            int nb = buf ^ 1;
            if (nb == 0) { STORE_TILE(As[0], Wsm[0], na0, na1, nw0, nw1) }
            else         { STORE_TILE(As[1], Wsm[1], na0, na1, nw0, nw1) }
            __syncthreads();
            buf = nb;
        }
    }
#pragma unroll
    for (int i = 0; i < 8; i++) {
        int r = rowR[ty * 8 + i];
        if (r < 0) continue;
        float* cp = g_E + (size_t)r * 256 + col0 + tx * 4;
        if (addmode) {
            float4 c0 = *(float4*)cp, c1 = *(float4*)(cp + 64);
            c0.x += acc[i][0]; c0.y += acc[i][1]; c0.z += acc[i][2]; c0.w += acc[i][3];
            c1.x += acc[i][4]; c1.y += acc[i][5]; c1.z += acc[i][6]; c1.w += acc[i][7];
            *(float4*)cp = c0; *(float4*)(cp + 64) = c1;
        } else {
            *(float4*)cp        = make_float4(acc[i][0], acc[i][1], acc[i][2], acc[i][3]);
            *(float4*)(cp + 64) = make_float4(acc[i][4], acc[i][5], acc[i][6], acc[i][7]);
        }
    }
}

// ------------- dense C = A @ W^T (+bias), K=256, BK=16, ping-pong -------------
__global__ void __launch_bounds__(256)
gemm256(const float* __restrict__ A, const float* __restrict__ W,
        const float* __restrict__ bias, float* __restrict__ C) {
    __shared__ float As[2][16][132];
    __shared__ float Wsm[2][16][132];
    const int tid  = threadIdx.x;
    const int row0 = blockIdx.x * 128;
    const int col0 = blockIdx.y * 128;
    const int lr = tid >> 2;
    const int kq = (tid & 3) * 4;
    const int tx = tid & 15, ty = tid >> 4;

    const float* a0 = A + (size_t)(row0 + lr) * 256 + kq;
    const float* a1 = A + (size_t)(row0 + lr + 64) * 256 + kq;
    const float* w0 = W + (size_t)(col0 + lr) * 256 + kq;
    const float* w1 = W + (size_t)(col0 + lr + 64) * 256 + kq;

    float acc[8][8];
#pragma unroll
    for (int i = 0; i < 8; i++)
#pragma unroll
        for (int j = 0; j < 8; j++) acc[i][j] = 0.f;

    {   // prime buffer 0
        float4 ga0 = *(const float4*)a0;
        float4 ga1 = *(const float4*)a1;
        float4 gw0 = *(const float4*)w0;
        float4 gw1 = *(const float4*)w1;
        STORE_TILE(As[0], Wsm[0], ga0, ga1, gw0, gw1)
    }
    __syncthreads();

    int buf = 0;
#pragma unroll
    for (int k0 = 0; k0 < 256; k0 += 16) {
        float4 na0, na1, nw0, nw1;
        const bool more = (k0 + 16 < 256);
        if (more) {
            na0 = *(const float4*)(a0 + k0 + 16);
            na1 = *(const float4*)(a1 + k0 + 16);
            nw0 = *(const float4*)(w0 + k0 + 16);
            nw1 = *(const float4*)(w1 + k0 + 16);
        }
        if (buf == 0) { COMPUTE_TILE(As[0], Wsm[0]) }
        else          { COMPUTE_TILE(As[1], Wsm[1]) }
        if (more) {
            int nb = buf ^ 1;
            if (nb == 0) { STORE_TILE(As[0], Wsm[0], na0, na1, nw0, nw1) }
            else         { STORE_TILE(As[1], Wsm[1], na0, na1, nw0, nw1) }
            __syncthreads();
            buf = nb;
        }
    }
    float bj[8];
#pragma unroll
    for (int j = 0; j < 4; j++) {
        bj[j]     = bias ? bias[col0 + tx * 4 + j]      : 0.f;
        bj[j + 4] = bias ? bias[col0 + tx * 4 + 64 + j] : 0.f;
    }
#pragma unroll
    for (int i = 0; i < 8; i++) {
        float* cp = C + (size_t)(row0 + ty * 8 + i) * 256 + col0 + tx * 4;
        *(float4*)cp        = make_float4(acc[i][0]+bj[0], acc[i][1]+bj[1], acc[i][2]+bj[2], acc[i][3]+bj[3]);
        *(float4*)(cp + 64) = make_float4(acc[i][4]+bj[4], acc[i][5]+bj[5], acc[i][6]+bj[6], acc[i][7]+bj[7]);
    }
}

// ------------- qt = relu(E[b,4] + max(0, Z[b,0..4])) --------------------------
__global__ void qt_kernel() {
    int i = blockIdx.x * 256 + threadIdx.x;     // over Bsz*256
    int b = i >> 8, h = i & 255;
    const float* zp = g_Z + (size_t)b * 5 * 256 + h;
    float st = fmaxf(0.f, zp[0]);
    st = fmaxf(st, zp[256]);
    st = fmaxf(st, zp[512]);
    st = fmaxf(st, zp[768]);
    st = fmaxf(st, zp[1024]);
    float e4 = g_E[(size_t)(b * 5 + 4) * 256 + h];
    g_qt[i] = fmaxf(e4 + st, 0.f);
}

// ------------- att[b,l] = 10*tanh(where(mask, sum_h V*tanh(inp+ctx), NEG)) ----
__global__ void __launch_bounds__(256)
att_kernel(const int* __restrict__ mask, const float* __restrict__ V) {
    int warp = blockIdx.x * 8 + (threadIdx.x >> 5);
    int lane = threadIdx.x & 31;
    int b = warp / 7;
    const float* ctxr = g_ctx + (size_t)warp * 256;
    const float* inpr = g_inp + (size_t)b * 256;
    float s = 0.f;
#pragma unroll
    for (int i = 0; i < 8; i++) {
        int h = i * 32 + lane;
        s += V[h] * xtanh(inpr[h] + ctxr[h]);
    }
#pragma unroll
    for (int off = 16; off > 0; off >>= 1)
        s += __shfl_down_sync(0xffffffffu, s, off);
    if (lane == 0) {
        float a = mask[warp] ? s : NEGV;
        g_att[warp] = 10.0f * xtanh(a);
    }
}

// ------------- per-column (axis=0) max and exp-sum ----------------------------
__global__ void colred() {
    int l = blockIdx.x, tid = threadIdx.x;
    __shared__ float red[256];
    float m = -3.4e38f;
    for (int b = tid; b < Bsz; b += 256) m = fmaxf(m, g_att[b * 7 + l]);
    red[tid] = m; __syncthreads();
    for (int s = 128; s > 0; s >>= 1) {
        if (tid < s) red[tid] = fmaxf(red[tid], red[tid + s]);
        __syncthreads();
    }
    float cm = red[0]; __syncthreads();
    float su = 0.f;
    for (int b = tid; b < Bsz; b += 256) su += expf(g_att[b * 7 + l] - cm);
    red[tid] = su; __syncthreads();
    for (int s = 128; s > 0; s >>= 1) {
        if (tid < s) red[tid] += red[tid + s];
        __syncthreads();
    }
    if (tid == 0) { g_cmax[l] = cm; g_csum[l] = red[0]; }
}

// ------------- alpha, gumbel, argmax, outputs ---------------------------------
__global__ void sample_kernel(const int* __restrict__ mask, float* __restrict__ out) {
    int b = blockIdx.x * 256 + threadIdx.x;
    if (b >= Bsz) return;
    float alpha[7], y[7];
#pragma unroll
    for (int l = 0; l < Lq; l++) {
        float e = expf(g_att[b * 7 + l] - g_cmax[l]);
        alpha[l] = __fdiv_rn(e, g_csum[l]);
        unsigned bits = jax_bits((unsigned)(b * 7 + l));
        float f = __uint_as_float((bits >> 9) | 0x3f800000u) - 1.0f;
        float u = (f > 0.f) ? f : 1.17549435e-38f;     // jax uniform [tiny, 1)
        float g = -logf(-logf(u));
        y[l] = g + logf(alpha[l]);
    }
    int idx = 0; float best = y[0];
#pragma unroll
    for (int l = 1; l < Lq; l++)
        if (y[l] > best) { best = y[l]; idx = l; }     // first-max like jnp.argmax
    out[b]        = (float)idx;
    out[Bsz + b]  = alpha[idx];
#pragma unroll
    for (int l = 0; l < Lq; l++)
        out[2 * Bsz + (size_t)b * 7 + l] = (float)(mask[b * 7 + l] - (l == idx ? 1 : 0));
}

// ------------- launch ---------------------------------------------------------
extern "C" void kernel_launch(void* const* d_in, const int* in_sizes, int n_in,
                              void* d_out, int out_size) {
    const float* enc  = (const float*)d_in[0];
    const void*  xes  = d_in[1];
    const int*   mask = (const int*)d_in[2];
    const float* Wh   = (const float*)d_in[3];
    const float* Wv   = (const float*)d_in[4];
    const float* Wsh  = (const float*)d_in[5];
    const float* Wsv  = (const float*)d_in[6];
    const float* We   = (const float*)d_in[7];
    const float* Win  = (const float*)d_in[8];
    const float* bin  = (const float*)d_in[9];
    const float* Wctx = (const float*)d_in[10];
    const float* bctx = (const float*)d_in[11];
    const float* V    = (const float*)d_in[12];
    float* out = (float*)d_out;

    float *pE, *pZ, *pqt, *pinp, *pctx;
    cudaGetSymbolAddress((void**)&pE,   g_E);
    cudaGetSymbolAddress((void**)&pZ,   g_Z);
    cudaGetSymbolAddress((void**)&pqt,  g_qt);
    cudaGetSymbolAddress((void**)&pinp, g_inp);
    cudaGetSymbolAddress((void**)&pctx, g_ctx);

    detect_kernel<<<1, 32>>>((const unsigned*)xes);

    // bucket rows by cond = (t==0)
    bcount  <<<NBLK, 256>>>(xes);
    bscan   <<<1, 1024>>>();
    bscatter<<<NBLK, 256>>>(xes);

    // edge passes (bit-exact vs reference: h-gemm then +v-gemm, k ascending)
    dim3 gE(M1 / 128 + 1, 2);
    edge_gemm<<<gE, 256>>>(enc, xes, Wh, Wsh, 0, 0);   // h-side
    edge_gemm<<<gE, 256>>>(enc, xes, Wv, Wsv, 1, 1);   // v-side, E += ...

    gemm256<<<dim3(M1 / 128, 2), 256>>>(pE, We, nullptr, pZ);        // Z = E @ We^T
    qt_kernel<<<Bsz, 256>>>();
    gemm256<<<dim3(Bsz / 128, 2), 256>>>(pqt, Win, bin, pinp);       // inp
    gemm256<<<dim3(BLq / 128, 2), 256>>>(enc, Wctx, bctx, pctx);     // ctx
    att_kernel<<<BLq / 8, 256>>>(mask, V);
    colred<<<Lq, 256>>>();
    sample_kernel<<<Bsz / 256, 256>>>(mask, out);
}

// round 15
// speedup vs baseline: 2.1857x; 2.1857x over previous
#include <cuda_runtime.h>

#define Bsz   32768
#define Lq    7
#define NSTEP 5
#define M1    (Bsz*NSTEP)          /* 163840 rows (b,t) t<5 */
#define BLq   (Bsz*Lq)             /* 229376 */
#define NEGV  -1000000000.0f
#define NBLK  640                  /* M1/256 */

// ------------- static device scratch (no allocation APIs anywhere) -------------
static __device__ float g_E  [(size_t)M1 * 256];   // edges
static __device__ float g_Z  [(size_t)M1 * 256];   // edge @ W_edge^T
static __device__ float g_qt [(size_t)Bsz * 256];
static __device__ float g_inp[(size_t)Bsz * 256];
static __device__ float g_ctx[(size_t)BLq * 256];  // (b*7+l, h)
static __device__ float g_att[BLq];
static __device__ float g_cmax[Lq];
static __device__ float g_csum[Lq];
static __device__ int   g_x64;                     // 1 if xes is int64 on device
static __device__ int   g_cntA[NBLK];              // per-block cond counts -> exclusive scan
static __device__ int   g_nA;                      // total cond rows
static __device__ int   g_perm[M1];                // bucket A rows [0,nA), bucket B [nA,M1)

// ------------- XLA/Eigen f32 tanh (rational approx, clamp 7.90531110763549805) ---
__device__ __forceinline__ float xtanh(float x) {
    float ax = fabsf(x);
    if (ax < 0.0004f) return x;
    float cx = fminf(fmaxf(x, -7.90531110763549805f), 7.90531110763549805f);
    float x2 = cx * cx;
    float p = fmaf(x2, -2.76076847742355e-16f, 2.00018790482477e-13f);
    p = fmaf(p, x2, -8.60467152213735e-11f);
    p = fmaf(p, x2,  5.12229709037114e-08f);
    p = fmaf(p, x2,  1.48572235717979e-05f);
    p = fmaf(p, x2,  6.37261928875436e-04f);
    p = fmaf(p, x2,  4.89352455891786e-03f);
    p = cx * p;
    float q = fmaf(x2, 1.19825839466702e-06f, 1.18534705686654e-04f);
    q = fmaf(q, x2, 2.26843463243900e-03f);
    q = fmaf(q, x2, 4.89352518554385e-03f);
    return __fdiv_rn(p, q);
}

// ------------- threefry2x32, key = (0, 42), 20 rounds ------------------------
#define TFR(r) { x0 += x1; x1 = (x1 << (r)) | (x1 >> (32 - (r))); x1 ^= x0; }
__device__ __forceinline__ void threefry42(unsigned c0, unsigned c1,
                                           unsigned& o0, unsigned& o1) {
    const unsigned ks0 = 0u, ks1 = 42u, ks2 = 0x1BD11BDAu ^ 0u ^ 42u;
    unsigned x0 = c0 + ks0, x1 = c1 + ks1;
    TFR(13) TFR(15) TFR(26) TFR(6)   x0 += ks1; x1 += ks2 + 1u;
    TFR(17) TFR(29) TFR(16) TFR(24)  x0 += ks2; x1 += ks0 + 2u;
    TFR(13) TFR(15) TFR(26) TFR(6)   x0 += ks0; x1 += ks1 + 3u;
    TFR(17) TFR(29) TFR(16) TFR(24)  x0 += ks1; x1 += ks2 + 4u;
    TFR(13) TFR(15) TFR(26) TFR(6)   x0 += ks2; x1 += ks0 + 5u;
    o0 = x0; o1 = x1;
}

__device__ __forceinline__ unsigned jax_bits(unsigned j) {
    unsigned o0, o1;
    threefry42(0u, j, o0, o1);      // partitionable threefry: bits = o0 ^ o1
    return o0 ^ o1;
}

// ------------- xes fetch (int64 vs int32, detected on device) ------------------
__device__ __forceinline__ void fetch_x(const void* xraw, int b, int t,
                                        int& hi, int& vi, int& tv) {
    if (g_x64) {
        const long long* xp = (const long long*)xraw + ((size_t)b * 6 + t) * 3;
        hi = (int)xp[0]; vi = (int)xp[1]; tv = (int)xp[2];
    } else {
        const int* xp = (const int*)xraw + ((size_t)b * 6 + t) * 3;
        hi = xp[0]; vi = xp[1]; tv = xp[2];
    }
}

__global__ void detect_kernel(const unsigned* __restrict__ x) {
    if (threadIdx.x == 0 && blockIdx.x == 0) {
        int a = 1;
        for (int k = 0; k < 256; k++)
            if (x[2 * k + 1] != 0u) { a = 0; break; }
        g_x64 = a;
    }
}

// ------------- bucketing: partition rows r=b*5+t by cond=(t_val==0) -----------
__global__ void bcount(const void* __restrict__ xraw) {
    int tid = threadIdx.x, blk = blockIdx.x;
    int r = blk * 256 + tid;
    int b = r / 5, t = r - b * 5;
    int hi, vi, tv; fetch_x(xraw, b, t, hi, vi, tv);
    int c = __syncthreads_count(tv == 0);
    if (tid == 0) g_cntA[blk] = c;
}

__global__ void bscan() {
    __shared__ int s[1024];
    int tid = threadIdx.x;
    int v = (tid < NBLK) ? g_cntA[tid] : 0;
    s[tid] = v; __syncthreads();
    for (int off = 1; off < 1024; off <<= 1) {
        int t = (tid >= off) ? s[tid - off] : 0;
        __syncthreads();
        s[tid] += t; __syncthreads();
    }
    if (tid < NBLK) g_cntA[tid] = s[tid] - v;     // exclusive
    if (tid == NBLK - 1) g_nA = s[tid];
}

__global__ void bscatter(const void* __restrict__ xraw) {
    int tid = threadIdx.x, blk = blockIdx.x;
    int r = blk * 256 + tid;
    int b = r / 5, t = r - b * 5;
    int hi, vi, tv; fetch_x(xraw, b, t, hi, vi, tv);
    bool cond = (tv == 0);
    unsigned m = __ballot_sync(0xffffffffu, cond);
    int lane = tid & 31, w = tid >> 5;
    __shared__ int wA[8], wOffA[8];
    int lrA = __popc(m & ((1u << lane) - 1u));
    if (lane == 0) wA[w] = __popc(m);
    __syncthreads();
    if (tid == 0) { int s = 0; for (int i = 0; i < 8; i++) { wOffA[i] = s; s += wA[i]; } }
    __syncthreads();
    int nA = g_nA;
    int baseA = g_cntA[blk];
    int baseB = blk * 256 - baseA;
    int lrB   = lane - lrA;
    int wOffB = w * 32 - wOffA[w];
    int pos = cond ? (baseA + wOffA[w] + lrA)
                   : (nA + baseB + wOffB + lrB);
    g_perm[pos] = r;
}

// ====== BK=32 helpers: store one float4 (transposed) into smem tile ======
#define STORE4(BUF, ROW, V)                                                      \
    BUF[kq8 + 0][ROW] = V.x; BUF[kq8 + 1][ROW] = V.y;                            \
    BUF[kq8 + 2][ROW] = V.z; BUF[kq8 + 3][ROW] = V.w;

// compute 16 kk steps starting at KH (keeps inner body ~17KB; outer not unrolled)
#define COMPUTE16(KH)                                                            \
    _Pragma("unroll")                                                            \
    for (int kk2 = 0; kk2 < 16; kk2++) {                                         \
        const int kk = (KH) + kk2;                                               \
        float a[8], w[8];                                                        \
        *(float4*)(a)     = *(const float4*)&As[kk][ty * 8];                     \
        *(float4*)(a + 4) = *(const float4*)&As[kk][ty * 8 + 4];                 \
        *(float4*)(w)     = *(const float4*)&Wsm[kk][tx * 4];                    \
        *(float4*)(w + 4) = *(const float4*)&Wsm[kk][tx * 4 + 64];               \
        _Pragma("unroll")                                                        \
        for (int i = 0; i < 8; i++)                                              \
            _Pragma("unroll")                                                    \
            for (int j = 0; j < 8; j++)                                          \
                acc[i][j] = fmaf(a[i], w[j], acc[i][j]);                         \
    }

// ------------- bucketed edge GEMM, K=256, 128x128 tile, BK=32 -----------------
// Per-output chain is k-ascending fmaf: bit-identical to the reference per-gemm
// chain. Two passes (h then v-add) reproduce "gemm1 + gemm2" exactly.
__global__ void __launch_bounds__(256, 2)
edge_gemm(const float* __restrict__ enc, const void* __restrict__ xraw,
          const float* __restrict__ Wcond, const float* __restrict__ Wother,
          int xcol, int addmode) {
    __shared__ float As[32][132];
    __shared__ float Wsm[32][132];
    __shared__ const float* Ap[128];
    __shared__ int rowR[128];

    const int tid  = threadIdx.x;
    const int tile = blockIdx.x;
    const int col0 = blockIdx.y * 128;

    const int nA = g_nA, nB = M1 - nA;
    const int tilesA = (nA + 127) >> 7;
    const int tilesB = (nB + 127) >> 7;
    if (tile >= tilesA + tilesB) return;
    const bool bb = (tile >= tilesA);

    if (tid < 128) {
        int j   = bb ? (tile - tilesA) * 128 + tid : tile * 128 + tid;
        int cnt = bb ? nB : nA;
        int r = -1;
        const float* ap = enc;
        if (j < cnt) {
            r = g_perm[bb ? nA + j : j];
            int b = r / 5, t = r - b * 5;
            int hi, vi, tv; fetch_x(xraw, b, t, hi, vi, tv);
            int sel = xcol ? vi : hi;
            ap = enc + ((size_t)b * 7 + sel) * 256;
        }
        rowR[tid] = r; Ap[tid] = ap;
    }
    __syncthreads();

    const float* W = bb ? Wother : Wcond;
    const int lr8 = tid >> 3;           // 0..31
    const int kq8 = (tid & 7) * 4;      // 0,4,...,28
    const int tx = tid & 15, ty = tid >> 4;

    const float* ar0 = Ap[lr8]      + kq8;
    const float* ar1 = Ap[lr8 + 32] + kq8;
    const float* ar2 = Ap[lr8 + 64] + kq8;
    const float* ar3 = Ap[lr8 + 96] + kq8;
    const float* wr  = W + (size_t)(col0 + lr8) * 256 + kq8;   // +32/+64/+96 rows via imm offsets

    float acc[8][8];
#pragma unroll
    for (int i = 0; i < 8; i++)
#pragma unroll
        for (int j = 0; j < 8; j++) acc[i][j] = 0.f;

    float4 ga0 = *(const float4*)ar0;
    float4 ga1 = *(const float4*)ar1;
    float4 ga2 = *(const float4*)ar2;
    float4 ga3 = *(const float4*)ar3;
    float4 gw0 = *(const float4*)(wr);
    float4 gw1 = *(const float4*)(wr + 32 * 256);
    float4 gw2 = *(const float4*)(wr + 64 * 256);
    float4 gw3 = *(const float4*)(wr + 96 * 256);

#pragma unroll 1
    for (int k0 = 0; k0 < 256; k0 += 32) {
        STORE4(As,  lr8,      ga0) STORE4(As,  lr8 + 32, ga1)
        STORE4(As,  lr8 + 64, ga2) STORE4(As,  lr8 + 96, ga3)
        STORE4(Wsm, lr8,      gw0) STORE4(Wsm, lr8 + 32, gw1)
        STORE4(Wsm, lr8 + 64, gw2) STORE4(Wsm, lr8 + 96, gw3)
        __syncthreads();
        if (k0 < 224) {
            ga0 = *(const float4*)(ar0 + k0 + 32);
            ga1 = *(const float4*)(ar1 + k0 + 32);
            ga2 = *(const float4*)(ar2 + k0 + 32);
            ga3 = *(const float4*)(ar3 + k0 + 32);
            gw0 = *(const float4*)(wr + k0 + 32);
            gw1 = *(const float4*)(wr + 32 * 256 + k0 + 32);
            gw2 = *(const float4*)(wr + 64 * 256 + k0 + 32);
            gw3 = *(const float4*)(wr + 96 * 256 + k0 + 32);
        }
        COMPUTE16(0)
        COMPUTE16(16)
        __syncthreads();
    }
#pragma unroll
    for (int i = 0; i < 8; i++) {
        int r = rowR[ty * 8 + i];
        if (r < 0) continue;
        float* cp = g_E + (size_t)r * 256 + col0 + tx * 4;
        if (addmode) {
            float4 c0 = *(float4*)cp, c1 = *(float4*)(cp + 64);
            c0.x += acc[i][0]; c0.y += acc[i][1]; c0.z += acc[i][2]; c0.w += acc[i][3];
            c1.x += acc[i][4]; c1.y += acc[i][5]; c1.z += acc[i][6]; c1.w += acc[i][7];
            *(float4*)cp = c0; *(float4*)(cp + 64) = c1;
        } else {
            *(float4*)cp        = make_float4(acc[i][0], acc[i][1], acc[i][2], acc[i][3]);
            *(float4*)(cp + 64) = make_float4(acc[i][4], acc[i][5], acc[i][6], acc[i][7]);
        }
    }
}

// ------------- dense C = A @ W^T (+bias), K=256, BK=32 ------------------------
__global__ void __launch_bounds__(256, 2)
gemm256(const float* __restrict__ A, const float* __restrict__ W,
        const float* __restrict__ bias, float* __restrict__ C) {
    __shared__ float As[32][132];
    __shared__ float Wsm[32][132];
    const int tid  = threadIdx.x;
    const int row0 = blockIdx.x * 128;
    const int col0 = blockIdx.y * 128;
    const int lr8 = tid >> 3;
    const int kq8 = (tid & 7) * 4;
    const int tx = tid & 15, ty = tid >> 4;

    const float* ar = A + (size_t)(row0 + lr8) * 256 + kq8;
    const float* wr = W + (size_t)(col0 + lr8) * 256 + kq8;

    float acc[8][8];
#pragma unroll
    for (int i = 0; i < 8; i++)
#pragma unroll
        for (int j = 0; j < 8; j++) acc[i][j] = 0.f;

    float4 ga0 = *(const float4*)(ar);
    float4 ga1 = *(const float4*)(ar + 32 * 256);
    float4 ga2 = *(const float4*)(ar + 64 * 256);
    float4 ga3 = *(const float4*)(ar + 96 * 256);
    float4 gw0 = *(const float4*)(wr);
    float4 gw1 = *(const float4*)(wr + 32 * 256);
    float4 gw2 = *(const float4*)(wr + 64 * 256);
    float4 gw3 = *(const float4*)(wr + 96 * 256);

#pragma unroll 1
    for (int k0 = 0; k0 < 256; k0 += 32) {
        STORE4(As,  lr8,      ga0) STORE4(As,  lr8 + 32, ga1)
        STORE4(As,  lr8 + 64, ga2) STORE4(As,  lr8 + 96, ga3)
        STORE4(Wsm, lr8,      gw0) STORE4(Wsm, lr8 + 32, gw1)
        STORE4(Wsm, lr8 + 64, gw2) STORE4(Wsm, lr8 + 96, gw3)
        __syncthreads();
        if (k0 < 224) {
            ga0 = *(const float4*)(ar + k0 + 32);
            ga1 = *(const float4*)(ar + 32 * 256 + k0 + 32);
            ga2 = *(const float4*)(ar + 64 * 256 + k0 + 32);
            ga3 = *(const float4*)(ar + 96 * 256 + k0 + 32);
            gw0 = *(const float4*)(wr + k0 + 32);
            gw1 = *(const float4*)(wr + 32 * 256 + k0 + 32);
            gw2 = *(const float4*)(wr + 64 * 256 + k0 + 32);
            gw3 = *(const float4*)(wr + 96 * 256 + k0 + 32);
        }
        COMPUTE16(0)
        COMPUTE16(16)
        __syncthreads();
    }
    float bj[8];
#pragma unroll
    for (int j = 0; j < 4; j++) {
        bj[j]     = bias ? bias[col0 + tx * 4 + j]      : 0.f;
        bj[j + 4] = bias ? bias[col0 + tx * 4 + 64 + j] : 0.f;
    }
#pragma unroll
    for (int i = 0; i < 8; i++) {
        float* cp = C + (size_t)(row0 + ty * 8 + i) * 256 + col0 + tx * 4;
        *(float4*)cp        = make_float4(acc[i][0]+bj[0], acc[i][1]+bj[1], acc[i][2]+bj[2], acc[i][3]+bj[3]);
        *(float4*)(cp + 64) = make_float4(acc[i][4]+bj[4], acc[i][5]+bj[5], acc[i][6]+bj[6], acc[i][7]+bj[7]);
    }
}

// ------------- qt = relu(E[b,4] + max(0, Z[b,0..4])) --------------------------
__global__ void qt_kernel() {
    int i = blockIdx.x * 256 + threadIdx.x;     // over Bsz*256
    int b = i >> 8, h = i & 255;
    const float* zp = g_Z + (size_t)b * 5 * 256 + h;
    float st = fmaxf(0.f, zp[0]);
    st = fmaxf(st, zp[256]);
    st = fmaxf(st, zp[512]);
    st = fmaxf(st, zp[768]);
    st = fmaxf(st, zp[1024]);
    float e4 = g_E[(size_t)(b * 5 + 4) * 256 + h];
    g_qt[i] = fmaxf(e4 + st, 0.f);
}

// ------------- att[b,l] = 10*tanh(where(mask, sum_h V*tanh(inp+ctx), NEG)) ----
__global__ void __launch_bounds__(256)
att_kernel(const int* __restrict__ mask, const float* __restrict__ V) {
    int warp = blockIdx.x * 8 + (threadIdx.x >> 5);
    int lane = threadIdx.x & 31;
    int b = warp / 7;
    const float* ctxr = g_ctx + (size_t)warp * 256;
    const float* inpr = g_inp + (size_t)b * 256;
    float s = 0.f;
#pragma unroll
    for (int i = 0; i < 8; i++) {
        int h = i * 32 + lane;
        s += V[h] * xtanh(inpr[h] + ctxr[h]);
    }
#pragma unroll
    for (int off = 16; off > 0; off >>= 1)
        s += __shfl_down_sync(0xffffffffu, s, off);
    if (lane == 0) {
        float a = mask[warp] ? s : NEGV;
        g_att[warp] = 10.0f * xtanh(a);
    }
}

// ------------- per-column (axis=0) max and exp-sum ----------------------------
__global__ void colred() {
    int l = blockIdx.x, tid = threadIdx.x;
    __shared__ float red[256];
    float m = -3.4e38f;
    for (int b = tid; b < Bsz; b += 256) m = fmaxf(m, g_att[b * 7 + l]);
    red[tid] = m; __syncthreads();
    for (int s = 128; s > 0; s >>= 1) {
        if (tid < s) red[tid] = fmaxf(red[tid], red[tid + s]);
        __syncthreads();
    }
    float cm = red[0]; __syncthreads();
    float su = 0.f;
    for (int b = tid; b < Bsz; b += 256) su += expf(g_att[b * 7 + l] - cm);
    red[tid] = su; __syncthreads();
    for (int s = 128; s > 0; s >>= 1) {
        if (tid < s) red[tid] += red[tid + s];
        __syncthreads();
    }
    if (tid == 0) { g_cmax[l] = cm; g_csum[l] = red[0]; }
}

// ------------- alpha, gumbel, argmax, outputs ---------------------------------
__global__ void sample_kernel(const int* __restrict__ mask, float* __restrict__ out) {
    int b = blockIdx.x * 256 + threadIdx.x;
    if (b >= Bsz) return;
    float alpha[7], y[7];
#pragma unroll
    for (int l = 0; l < Lq; l++) {
        float e = expf(g_att[b * 7 + l] - g_cmax[l]);
        alpha[l] = __fdiv_rn(e, g_csum[l]);
        unsigned bits = jax_bits((unsigned)(b * 7 + l));
        float f = __uint_as_float((bits >> 9) | 0x3f800000u) - 1.0f;
        float u = (f > 0.f) ? f : 1.17549435e-38f;     // jax uniform [tiny, 1)
        float g = -logf(-logf(u));
        y[l] = g + logf(alpha[l]);
    }
    int idx = 0; float best = y[0];
#pragma unroll
    for (int l = 1; l < Lq; l++)
        if (y[l] > best) { best = y[l]; idx = l; }     // first-max like jnp.argmax
    out[b]        = (float)idx;
    out[Bsz + b]  = alpha[idx];
#pragma unroll
    for (int l = 0; l < Lq; l++)
        out[2 * Bsz + (size_t)b * 7 + l] = (float)(mask[b * 7 + l] - (l == idx ? 1 : 0));
}

// ------------- launch ---------------------------------------------------------
extern "C" void kernel_launch(void* const* d_in, const int* in_sizes, int n_in,
                              void* d_out, int out_size) {
    const float* enc  = (const float*)d_in[0];
    const void*  xes  = d_in[1];
    const int*   mask = (const int*)d_in[2];
    const float* Wh   = (const float*)d_in[3];
    const float* Wv   = (const float*)d_in[4];
    const float* Wsh  = (const float*)d_in[5];
    const float* Wsv  = (const float*)d_in[6];
    const float* We   = (const float*)d_in[7];
    const float* Win  = (const float*)d_in[8];
    const float* bin  = (const float*)d_in[9];
    const float* Wctx = (const float*)d_in[10];
    const float* bctx = (const float*)d_in[11];
    const float* V    = (const float*)d_in[12];
    float* out = (float*)d_out;

    float *pE, *pZ, *pqt, *pinp, *pctx;
    cudaGetSymbolAddress((void**)&pE,   g_E);
    cudaGetSymbolAddress((void**)&pZ,   g_Z);
    cudaGetSymbolAddress((void**)&pqt,  g_qt);
    cudaGetSymbolAddress((void**)&pinp, g_inp);
    cudaGetSymbolAddress((void**)&pctx, g_ctx);

    detect_kernel<<<1, 32>>>((const unsigned*)xes);        // launch 0

    // bucket rows by cond = (t==0)
    bcount  <<<NBLK, 256>>>(xes);                          // launch 1
    bscan   <<<1, 1024>>>();                               // launch 2

    // ctx gemm moved here (independent of bucketing) so ncu -s 5 profiles it
    gemm256<<<dim3(BLq / 128, 2), 256>>>(enc, Wctx, bctx, pctx);     // launch 3

    bscatter<<<NBLK, 256>>>(xes);                          // launch 4

    // edge passes (bit-exact vs reference: h-gemm then +v-gemm, k ascending)
    dim3 gE(M1 / 128 + 1, 2);
    edge_gemm<<<gE, 256>>>(enc, xes, Wh, Wsh, 0, 0);   // h-side
    edge_gemm<<<gE, 256>>>(enc, xes, Wv, Wsv, 1, 1);   // v-side, E += ...

    gemm256<<<dim3(M1 / 128, 2), 256>>>(pE, We, nullptr, pZ);        // Z = E @ We^T
    qt_kernel<<<Bsz, 256>>>();
    gemm256<<<dim3(Bsz / 128, 2), 256>>>(pqt, Win, bin, pinp);       // inp
    att_kernel<<<BLq / 8, 256>>>(mask, V);
    colred<<<Lq, 256>>>();
    sample_kernel<<<Bsz / 256, 256>>>(mask, out);
}

// round 16
// speedup vs baseline: 2.2136x; 1.0128x over previous
#include <cuda_runtime.h>

#define Bsz   32768
#define Lq    7
#define NSTEP 5
#define M1    (Bsz*NSTEP)          /* 163840 rows (b,t) t<5 */
#define BLq   (Bsz*Lq)             /* 229376 */
#define NEGV  -1000000000.0f
#define NBLK  640                  /* M1/256 */

// ------------- static device scratch (no allocation APIs anywhere) -------------
static __device__ float g_E  [(size_t)M1 * 256];   // edges
static __device__ float g_Z  [(size_t)M1 * 256];   // edge @ W_edge^T
static __device__ float g_qt [(size_t)Bsz * 256];
static __device__ float g_inp[(size_t)Bsz * 256];
static __device__ float g_ctx[(size_t)BLq * 256];  // (b*7+l, h)
static __device__ float g_att[BLq];
static __device__ float g_cmax[Lq];
static __device__ float g_csum[Lq];
static __device__ int   g_x64;                     // 1 if xes is int64 on device
static __device__ int   g_cntA[NBLK];              // per-block cond counts -> exclusive scan
static __device__ int   g_nA;                      // total cond rows
static __device__ int   g_perm[M1];                // bucket A rows [0,nA), bucket B [nA,M1)

// ------------- XLA/Eigen f32 tanh (rational approx, clamp 7.90531110763549805) ---
__device__ __forceinline__ float xtanh(float x) {
    float ax = fabsf(x);
    if (ax < 0.0004f) return x;
    float cx = fminf(fmaxf(x, -7.90531110763549805f), 7.90531110763549805f);
    float x2 = cx * cx;
    float p = fmaf(x2, -2.76076847742355e-16f, 2.00018790482477e-13f);
    p = fmaf(p, x2, -8.60467152213735e-11f);
    p = fmaf(p, x2,  5.12229709037114e-08f);
    p = fmaf(p, x2,  1.48572235717979e-05f);
    p = fmaf(p, x2,  6.37261928875436e-04f);
    p = fmaf(p, x2,  4.89352455891786e-03f);
    p = cx * p;
    float q = fmaf(x2, 1.19825839466702e-06f, 1.18534705686654e-04f);
    q = fmaf(q, x2, 2.26843463243900e-03f);
    q = fmaf(q, x2, 4.89352518554385e-03f);
    return __fdiv_rn(p, q);
}

// ------------- threefry2x32, key = (0, 42), 20 rounds ------------------------
#define TFR(r) { x0 += x1; x1 = (x1 << (r)) | (x1 >> (32 - (r))); x1 ^= x0; }
__device__ __forceinline__ void threefry42(unsigned c0, unsigned c1,
                                           unsigned& o0, unsigned& o1) {
    const unsigned ks0 = 0u, ks1 = 42u, ks2 = 0x1BD11BDAu ^ 0u ^ 42u;
    unsigned x0 = c0 + ks0, x1 = c1 + ks1;
    TFR(13) TFR(15) TFR(26) TFR(6)   x0 += ks1; x1 += ks2 + 1u;
    TFR(17) TFR(29) TFR(16) TFR(24)  x0 += ks2; x1 += ks0 + 2u;
    TFR(13) TFR(15) TFR(26) TFR(6)   x0 += ks0; x1 += ks1 + 3u;
    TFR(17) TFR(29) TFR(16) TFR(24)  x0 += ks1; x1 += ks2 + 4u;
    TFR(13) TFR(15) TFR(26) TFR(6)   x0 += ks2; x1 += ks0 + 5u;
    o0 = x0; o1 = x1;
}

__device__ __forceinline__ unsigned jax_bits(unsigned j) {
    unsigned o0, o1;
    threefry42(0u, j, o0, o1);      // partitionable threefry: bits = o0 ^ o1
    return o0 ^ o1;
}

// ------------- xes fetch (int64 vs int32, detected on device) ------------------
__device__ __forceinline__ void fetch_x(const void* xraw, int b, int t,
                                        int& hi, int& vi, int& tv) {
    if (g_x64) {
        const long long* xp = (const long long*)xraw + ((size_t)b * 6 + t) * 3;
        hi = (int)xp[0]; vi = (int)xp[1]; tv = (int)xp[2];
    } else {
        const int* xp = (const int*)xraw + ((size_t)b * 6 + t) * 3;
        hi = xp[0]; vi = xp[1]; tv = xp[2];
    }
}

__global__ void detect_kernel(const unsigned* __restrict__ x) {
    if (threadIdx.x == 0 && blockIdx.x == 0) {
        int a = 1;
        for (int k = 0; k < 256; k++)
            if (x[2 * k + 1] != 0u) { a = 0; break; }
        g_x64 = a;
    }
}

// ------------- bucketing: partition rows r=b*5+t by cond=(t_val==0) -----------
__global__ void bcount(const void* __restrict__ xraw) {
    int tid = threadIdx.x, blk = blockIdx.x;
    int r = blk * 256 + tid;
    int b = r / 5, t = r - b * 5;
    int hi, vi, tv; fetch_x(xraw, b, t, hi, vi, tv);
    int c = __syncthreads_count(tv == 0);
    if (tid == 0) g_cntA[blk] = c;
}

__global__ void bscan() {
    __shared__ int s[1024];
    int tid = threadIdx.x;
    int v = (tid < NBLK) ? g_cntA[tid] : 0;
    s[tid] = v; __syncthreads();
    for (int off = 1; off < 1024; off <<= 1) {
        int t = (tid >= off) ? s[tid - off] : 0;
        __syncthreads();
        s[tid] += t; __syncthreads();
    }
    if (tid < NBLK) g_cntA[tid] = s[tid] - v;     // exclusive
    if (tid == NBLK - 1) g_nA = s[tid];
}

__global__ void bscatter(const void* __restrict__ xraw) {
    int tid = threadIdx.x, blk = blockIdx.x;
    int r = blk * 256 + tid;
    int b = r / 5, t = r - b * 5;
    int hi, vi, tv; fetch_x(xraw, b, t, hi, vi, tv);
    bool cond = (tv == 0);
    unsigned m = __ballot_sync(0xffffffffu, cond);
    int lane = tid & 31, w = tid >> 5;
    __shared__ int wA[8], wOffA[8];
    int lrA = __popc(m & ((1u << lane) - 1u));
    if (lane == 0) wA[w] = __popc(m);
    __syncthreads();
    if (tid == 0) { int s = 0; for (int i = 0; i < 8; i++) { wOffA[i] = s; s += wA[i]; } }
    __syncthreads();
    int nA = g_nA;
    int baseA = g_cntA[blk];
    int baseB = blk * 256 - baseA;
    int lrB   = lane - lrA;
    int wOffB = w * 32 - wOffA[w];
    int pos = cond ? (baseA + wOffA[w] + lrA)
                   : (nA + baseB + wOffB + lrB);
    g_perm[pos] = r;
}

// ------------- bucketed edge GEMM (R13 known-good): K=256, BK=16 --------------
// Per-output chain is k-ascending fmaf: bit-identical to the reference per-gemm
// chain. Two passes (h then v-add) reproduce "gemm1 + gemm2" exactly.
__global__ void __launch_bounds__(256)
edge_gemm(const float* __restrict__ enc, const void* __restrict__ xraw,
          const float* __restrict__ Wcond, const float* __restrict__ Wother,
          int xcol, int addmode) {
    __shared__ float As[16][132];
    __shared__ float Wsm[16][132];
    __shared__ const float* Ap[128];
    __shared__ int rowR[128];

    const int tid  = threadIdx.x;
    const int tile = blockIdx.x;
    const int col0 = blockIdx.y * 128;

    const int nA = g_nA, nB = M1 - nA;
    const int tilesA = (nA + 127) >> 7;
    const int tilesB = (nB + 127) >> 7;
    if (tile >= tilesA + tilesB) return;
    const bool bb = (tile >= tilesA);

    if (tid < 128) {
        int j   = bb ? (tile - tilesA) * 128 + tid : tile * 128 + tid;
        int cnt = bb ? nB : nA;
        int r = -1;
        const float* ap = enc;
        if (j < cnt) {
            r = g_perm[bb ? nA + j : j];
            int b = r / 5, t = r - b * 5;
            int hi, vi, tv; fetch_x(xraw, b, t, hi, vi, tv);
            int sel = xcol ? vi : hi;
            ap = enc + ((size_t)b * 7 + sel) * 256;
        }
        rowR[tid] = r; Ap[tid] = ap;
    }
    __syncthreads();

    const float* W = bb ? Wother : Wcond;
    const int lr = tid >> 2;            // 0..63
    const int kq = (tid & 3) * 4;       // 0,4,8,12
    const int tx = tid & 15, ty = tid >> 4;

    const float* a0 = Ap[lr]      + kq;
    const float* a1 = Ap[lr + 64] + kq;
    const float* w0 = W + (size_t)(col0 + lr) * 256 + kq;
    const float* w1 = W + (size_t)(col0 + lr + 64) * 256 + kq;

    float acc[8][8];
#pragma unroll
    for (int i = 0; i < 8; i++)
#pragma unroll
        for (int j = 0; j < 8; j++) acc[i][j] = 0.f;

    float4 ga0 = *(const float4*)a0;
    float4 ga1 = *(const float4*)a1;
    float4 gw0 = *(const float4*)w0;
    float4 gw1 = *(const float4*)w1;

    for (int k0 = 0; k0 < 256; k0 += 16) {
        As [kq+0][lr]    = ga0.x; As [kq+1][lr]    = ga0.y; As [kq+2][lr]    = ga0.z; As [kq+3][lr]    = ga0.w;
        As [kq+0][lr+64] = ga1.x; As [kq+1][lr+64] = ga1.y; As [kq+2][lr+64] = ga1.z; As [kq+3][lr+64] = ga1.w;
        Wsm[kq+0][lr]    = gw0.x; Wsm[kq+1][lr]    = gw0.y; Wsm[kq+2][lr]    = gw0.z; Wsm[kq+3][lr]    = gw0.w;
        Wsm[kq+0][lr+64] = gw1.x; Wsm[kq+1][lr+64] = gw1.y; Wsm[kq+2][lr+64] = gw1.z; Wsm[kq+3][lr+64] = gw1.w;
        __syncthreads();
        if (k0 < 240) {
            ga0 = *(const float4*)(a0 + k0 + 16);
            ga1 = *(const float4*)(a1 + k0 + 16);
            gw0 = *(const float4*)(w0 + k0 + 16);
            gw1 = *(const float4*)(w1 + k0 + 16);
        }
#pragma unroll
        for (int kk = 0; kk < 16; kk++) {
            float a[8], w[8];
            *(float4*)(a)     = *(const float4*)&As [kk][ty * 8];
            *(float4*)(a + 4) = *(const float4*)&As [kk][ty * 8 + 4];
            *(float4*)(w)     = *(const float4*)&Wsm[kk][tx * 4];
            *(float4*)(w + 4) = *(const float4*)&Wsm[kk][tx * 4 + 64];
#pragma unroll
            for (int i = 0; i < 8; i++)
#pragma unroll
                for (int j = 0; j < 8; j++)
                    acc[i][j] = fmaf(a[i], w[j], acc[i][j]);
        }
        __syncthreads();
    }
#pragma unroll
    for (int i = 0; i < 8; i++) {
        int r = rowR[ty * 8 + i];
        if (r < 0) continue;
        float* cp = g_E + (size_t)r * 256 + col0 + tx * 4;
        if (addmode) {
            float4 c0 = *(float4*)cp, c1 = *(float4*)(cp + 64);
            c0.x += acc[i][0]; c0.y += acc[i][1]; c0.z += acc[i][2]; c0.w += acc[i][3];
            c1.x += acc[i][4]; c1.y += acc[i][5]; c1.z += acc[i][6]; c1.w += acc[i][7];
            *(float4*)cp = c0; *(float4*)(cp + 64) = c1;
        } else {
            *(float4*)cp        = make_float4(acc[i][0], acc[i][1], acc[i][2], acc[i][3]);
            *(float4*)(cp + 64) = make_float4(acc[i][4], acc[i][5], acc[i][6], acc[i][7]);
        }
    }
}

// ====== BK=32 helpers for gemm256 ======
#define STORE4(BUF, ROW, V)                                                      \
    BUF[kq8 + 0][ROW] = V.x; BUF[kq8 + 1][ROW] = V.y;                            \
    BUF[kq8 + 2][ROW] = V.z; BUF[kq8 + 3][ROW] = V.w;

#define COMPUTE16(KH)                                                            \
    _Pragma("unroll")                                                            \
    for (int kk2 = 0; kk2 < 16; kk2++) {                                         \
        const int kk = (KH) + kk2;                                               \
        float a[8], w[8];                                                        \
        *(float4*)(a)     = *(const float4*)&As[kk][ty * 8];                     \
        *(float4*)(a + 4) = *(const float4*)&As[kk][ty * 8 + 4];                 \
        *(float4*)(w)     = *(const float4*)&Wsm[kk][tx * 4];                    \
        *(float4*)(w + 4) = *(const float4*)&Wsm[kk][tx * 4 + 64];               \
        _Pragma("unroll")                                                        \
        for (int i = 0; i < 8; i++)                                              \
            _Pragma("unroll")                                                    \
            for (int j = 0; j < 8; j++)                                          \
                acc[i][j] = fmaf(a[i], w[j], acc[i][j]);                         \
    }

// ------------- dense C = A @ W^T (+bias), K=256, BK=32, maxregs ---------------
// __launch_bounds__(256,1): free register budget so ptxas pipelines LDS/LDG.
__global__ void __launch_bounds__(256, 1)
gemm256(const float* __restrict__ A, const float* __restrict__ W,
        const float* __restrict__ bias, float* __restrict__ C) {
    __shared__ float As[32][132];
    __shared__ float Wsm[32][132];
    const int tid  = threadIdx.x;
    const int row0 = blockIdx.x * 128;
    const int col0 = blockIdx.y * 128;
    const int lr8 = tid >> 3;           // 0..31
    const int kq8 = (tid & 7) * 4;      // 0,4,...,28
    const int tx = tid & 15, ty = tid >> 4;

    const float* ar = A + (size_t)(row0 + lr8) * 256 + kq8;
    const float* wr = W + (size_t)(col0 + lr8) * 256 + kq8;

    float acc[8][8];
#pragma unroll
    for (int i = 0; i < 8; i++)
#pragma unroll
        for (int j = 0; j < 8; j++) acc[i][j] = 0.f;

    float4 ga0 = *(const float4*)(ar);
    float4 ga1 = *(const float4*)(ar + 32 * 256);
    float4 ga2 = *(const float4*)(ar + 64 * 256);
    float4 ga3 = *(const float4*)(ar + 96 * 256);
    float4 gw0 = *(const float4*)(wr);
    float4 gw1 = *(const float4*)(wr + 32 * 256);
    float4 gw2 = *(const float4*)(wr + 64 * 256);
    float4 gw3 = *(const float4*)(wr + 96 * 256);

#pragma unroll 1
    for (int k0 = 0; k0 < 256; k0 += 32) {
        STORE4(As,  lr8,      ga0) STORE4(As,  lr8 + 32, ga1)
        STORE4(As,  lr8 + 64, ga2) STORE4(As,  lr8 + 96, ga3)
        STORE4(Wsm, lr8,      gw0) STORE4(Wsm, lr8 + 32, gw1)
        STORE4(Wsm, lr8 + 64, gw2) STORE4(Wsm, lr8 + 96, gw3)
        __syncthreads();
        if (k0 < 224) {
            ga0 = *(const float4*)(ar + k0 + 32);
            ga1 = *(const float4*)(ar + 32 * 256 + k0 + 32);
            ga2 = *(const float4*)(ar + 64 * 256 + k0 + 32);
            ga3 = *(const float4*)(ar + 96 * 256 + k0 + 32);
            gw0 = *(const float4*)(wr + k0 + 32);
            gw1 = *(const float4*)(wr + 32 * 256 + k0 + 32);
            gw2 = *(const float4*)(wr + 64 * 256 + k0 + 32);
            gw3 = *(const float4*)(wr + 96 * 256 + k0 + 32);
        }
        COMPUTE16(0)
        COMPUTE16(16)
        __syncthreads();
    }
    float bj[8];
#pragma unroll
    for (int j = 0; j < 4; j++) {
        bj[j]     = bias ? bias[col0 + tx * 4 + j]      : 0.f;
        bj[j + 4] = bias ? bias[col0 + tx * 4 + 64 + j] : 0.f;
    }
#pragma unroll
    for (int i = 0; i < 8; i++) {
        float* cp = C + (size_t)(row0 + ty * 8 + i) * 256 + col0 + tx * 4;
        *(float4*)cp        = make_float4(acc[i][0]+bj[0], acc[i][1]+bj[1], acc[i][2]+bj[2], acc[i][3]+bj[3]);
        *(float4*)(cp + 64) = make_float4(acc[i][4]+bj[4], acc[i][5]+bj[5], acc[i][6]+bj[6], acc[i][7]+bj[7]);
    }
}

// ------------- qt = relu(E[b,4] + max(0, Z[b,0..4])) --------------------------
__global__ void qt_kernel() {
    int i = blockIdx.x * 256 + threadIdx.x;     // over Bsz*256
    int b = i >> 8, h = i & 255;
    const float* zp = g_Z + (size_t)b * 5 * 256 + h;
    float st = fmaxf(0.f, zp[0]);
    st = fmaxf(st, zp[256]);
    st = fmaxf(st, zp[512]);
    st = fmaxf(st, zp[768]);
    st = fmaxf(st, zp[1024]);
    float e4 = g_E[(size_t)(b * 5 + 4) * 256 + h];
    g_qt[i] = fmaxf(e4 + st, 0.f);
}

// ------------- att[b,l] = 10*tanh(where(mask, sum_h V*tanh(inp+ctx), NEG)) ----
__global__ void __launch_bounds__(256)
att_kernel(const int* __restrict__ mask, const float* __restrict__ V) {
    int warp = blockIdx.x * 8 + (threadIdx.x >> 5);
    int lane = threadIdx.x & 31;
    int b = warp / 7;
    const float* ctxr = g_ctx + (size_t)warp * 256;
    const float* inpr = g_inp + (size_t)b * 256;
    float s = 0.f;
#pragma unroll
    for (int i = 0; i < 8; i++) {
        int h = i * 32 + lane;
        s += V[h] * xtanh(inpr[h] + ctxr[h]);
    }
#pragma unroll
    for (int off = 16; off > 0; off >>= 1)
        s += __shfl_down_sync(0xffffffffu, s, off);
    if (lane == 0) {
        float a = mask[warp] ? s : NEGV;
        g_att[warp] = 10.0f * xtanh(a);
    }
}

// ------------- per-column (axis=0) max and exp-sum ----------------------------
__global__ void colred() {
    int l = blockIdx.x, tid = threadIdx.x;
    __shared__ float red[256];
    float m = -3.4e38f;
    for (int b = tid; b < Bsz; b += 256) m = fmaxf(m, g_att[b * 7 + l]);
    red[tid] = m; __syncthreads();
    for (int s = 128; s > 0; s >>= 1) {
        if (tid < s) red[tid] = fmaxf(red[tid], red[tid + s]);
        __syncthreads();
    }
    float cm = red[0]; __syncthreads();
    float su = 0.f;
    for (int b = tid; b < Bsz; b += 256) su += expf(g_att[b * 7 + l] - cm);
    red[tid] = su; __syncthreads();
    for (int s = 128; s > 0; s >>= 1) {
        if (tid < s) red[tid] += red[tid + s];
        __syncthreads();
    }
    if (tid == 0) { g_cmax[l] = cm; g_csum[l] = red[0]; }
}

// ------------- alpha, gumbel, argmax, outputs ---------------------------------
__global__ void sample_kernel(const int* __restrict__ mask, float* __restrict__ out) {
    int b = blockIdx.x * 256 + threadIdx.x;
    if (b >= Bsz) return;
    float alpha[7], y[7];
#pragma unroll
    for (int l = 0; l < Lq; l++) {
        float e = expf(g_att[b * 7 + l] - g_cmax[l]);
        alpha[l] = __fdiv_rn(e, g_csum[l]);
        unsigned bits = jax_bits((unsigned)(b * 7 + l));
        float f = __uint_as_float((bits >> 9) | 0x3f800000u) - 1.0f;
        float u = (f > 0.f) ? f : 1.17549435e-38f;     // jax uniform [tiny, 1)
        float g = -logf(-logf(u));
        y[l] = g + logf(alpha[l]);
    }
    int idx = 0; float best = y[0];
#pragma unroll
    for (int l = 1; l < Lq; l++)
        if (y[l] > best) { best = y[l]; idx = l; }     // first-max like jnp.argmax
    out[b]        = (float)idx;
    out[Bsz + b]  = alpha[idx];
#pragma unroll
    for (int l = 0; l < Lq; l++)
        out[2 * Bsz + (size_t)b * 7 + l] = (float)(mask[b * 7 + l] - (l == idx ? 1 : 0));
}

// ------------- launch ---------------------------------------------------------
extern "C" void kernel_launch(void* const* d_in, const int* in_sizes, int n_in,
                              void* d_out, int out_size) {
    const float* enc  = (const float*)d_in[0];
    const void*  xes  = d_in[1];
    const int*   mask = (const int*)d_in[2];
    const float* Wh   = (const float*)d_in[3];
    const float* Wv   = (const float*)d_in[4];
    const float* Wsh  = (const float*)d_in[5];
    const float* Wsv  = (const float*)d_in[6];
    const float* We   = (const float*)d_in[7];
    const float* Win  = (const float*)d_in[8];
    const float* bin  = (const float*)d_in[9];
    const float* Wctx = (const float*)d_in[10];
    const float* bctx = (const float*)d_in[11];
    const float* V    = (const float*)d_in[12];
    float* out = (float*)d_out;

    float *pE, *pZ, *pqt, *pinp, *pctx;
    cudaGetSymbolAddress((void**)&pE,   g_E);
    cudaGetSymbolAddress((void**)&pZ,   g_Z);
    cudaGetSymbolAddress((void**)&pqt,  g_qt);
    cudaGetSymbolAddress((void**)&pinp, g_inp);
    cudaGetSymbolAddress((void**)&pctx, g_ctx);

    detect_kernel<<<1, 32>>>((const unsigned*)xes);        // launch 0

    // bucket rows by cond = (t==0)
    bcount  <<<NBLK, 256>>>(xes);                          // launch 1
    bscan   <<<1, 1024>>>();                               // launch 2

    // ctx gemm kept at launch 3 so ncu captures the new gemm256
    gemm256<<<dim3(BLq / 128, 2), 256>>>(enc, Wctx, bctx, pctx);     // launch 3

    bscatter<<<NBLK, 256>>>(xes);                          // launch 4

    // edge passes (bit-exact vs reference: h-gemm then +v-gemm, k ascending)
    dim3 gE(M1 / 128 + 1, 2);
    edge_gemm<<<gE, 256>>>(enc, xes, Wh, Wsh, 0, 0);   // h-side
    edge_gemm<<<gE, 256>>>(enc, xes, Wv, Wsv, 1, 1);   // v-side, E += ...

    gemm256<<<dim3(M1 / 128, 2), 256>>>(pE, We, nullptr, pZ);        // Z = E @ We^T
    qt_kernel<<<Bsz, 256>>>();
    gemm256<<<dim3(Bsz / 128, 2), 256>>>(pqt, Win, bin, pinp);       // inp
    att_kernel<<<BLq / 8, 256>>>(mask, V);
    colred<<<Lq, 256>>>();
    sample_kernel<<<Bsz / 256, 256>>>(mask, out);
}